// round 16
// baseline (speedup 1.0000x reference)
#include <cuda_runtime.h>
#include <cuda_fp16.h>
#include <cstdint>
#include <cstddef>

#define D_MODEL 2048
#define LSEQ    4096
#define BDIM    2
#define NTOK    (BDIM * LSEQ)      // 8192
#define NHEAD   16
#define HIDDEN  5632
#define NCHUNK  32
#define CLEN    (LSEQ / NCHUNK)    // 128

// ---------------- scratch (device globals; no allocation allowed) ----------------
__device__ __half g_xn [(size_t)NTOK * D_MODEL];
__device__ float  g_qk [(size_t)NTOK * 2048];             // q | k*scale
__device__ float  g_eg [(size_t)NTOK * 1024];
__device__ __half g_vh [(size_t)NTOK * D_MODEL];          // v (half)
__device__ __half g_gth[(size_t)NTOK * D_MODEL];          // g (half, bias included)
__device__ __half g_oh [(size_t)NTOK * D_MODEL];
__device__ float  g_x2 [(size_t)NTOK * D_MODEL];
__device__ __half g_h1h[(size_t)NTOK * HIDDEN];
__device__ __half g_wt [51380224];
__device__ float  g_Tc [(size_t)NCHUNK * 64 * 64 * 64];
__device__ float  g_Pc [(size_t)NCHUNK * 64 * 64];
__device__ float  g_Sst[(size_t)NCHUNK * 64 * 64 * 64];

__device__ __forceinline__ float siluf(float x) { return x / (1.f + __expf(-x)); }
__device__ __forceinline__ void cpa16(void* s, const void* g) {
    uint32_t a = (uint32_t)__cvta_generic_to_shared(s);
    asm volatile("cp.async.cg.shared.global [%0], [%1], 16;" :: "r"(a), "l"(g));
}

// ================= fp16 tensor-core GEMM (R10/R12 proven mainloop) =================
enum { EPI_QKVG = 0, EPI_RES = 3, EPI_SWIGLU = 5 };

#define BK    64
#define LDH   72
#define AH    (128 * LDH)
#define STGH  (2 * AH)
#define NST   3
#define GSMEM (NST * STGH * 2)             // 110592 B

#define LDSM4(r, a)                                                            \
    asm volatile("ldmatrix.sync.aligned.m8n8.x4.shared.b16 {%0,%1,%2,%3}, [%4];" \
        : "=r"((r)[0]), "=r"((r)[1]), "=r"((r)[2]), "=r"((r)[3]) : "r"(a))

__device__ __forceinline__ void mma_h(float* c, const uint32_t* a, const uint32_t* b) {
    asm volatile(
        "mma.sync.aligned.m16n8k16.row.col.f32.f16.f16.f32 "
        "{%0,%1,%2,%3}, {%4,%5,%6,%7}, {%8,%9}, {%0,%1,%2,%3};"
        : "+f"(c[0]), "+f"(c[1]), "+f"(c[2]), "+f"(c[3])
        : "r"(a[0]), "r"(a[1]), "r"(a[2]), "r"(a[3]), "r"(b[0]), "r"(b[1]));
}

template <int EPI>
__global__ __launch_bounds__(128, 2) void gemm_h(
    const __half* __restrict__ A, const __half* __restrict__ Wt, void* __restrict__ Cv,
    int M, int N, int K,
    const float* __restrict__ bias, const void* __restrict__ resv,
    const float* __restrict__ aux)
{
    extern __shared__ __align__(16) __half hsm[];
    const int tid = threadIdx.x;
    const int wid = tid >> 5, lane = tid & 31;
    const int g = lane >> 2, tig = lane & 3;
    const int wm = (wid >> 1) * 64;
    const int wn = (wid & 1) * 64;
    const int m0 = blockIdx.y * 128;
    const int n0 = blockIdx.x * 128;
    const int nK = K >> 6;

    auto load_stage = [&](int slot, int kc) {
        __half* As = hsm + slot * STGH;
        __half* Bs = As + AH;
        const int k0 = kc * BK;
        const __half* Ag = A  + (size_t)m0 * K + k0;
        const __half* Bg = Wt + (size_t)n0 * K + k0;
        #pragma unroll
        for (int j = 0; j < 8; j++) {
            const int i = tid + j * 128;
            const int row = i >> 3, c = i & 7;
            cpa16(As + row * LDH + c * 8, Ag + (size_t)row * K + c * 8);
            cpa16(Bs + row * LDH + c * 8, Bg + (size_t)row * K + c * 8);
        }
        asm volatile("cp.async.commit_group;");
    };

    float acc[4][8][4];
    #pragma unroll
    for (int mt = 0; mt < 4; mt++)
        #pragma unroll
        for (int nt = 0; nt < 8; nt++)
            #pragma unroll
            for (int r = 0; r < 4; r++) acc[mt][nt][r] = 0.f;

    load_stage(0, 0);
    load_stage(1, 1);

    const uint32_t sbase = (uint32_t)__cvta_generic_to_shared(hsm);
    const int lrA = lane & 15;
    const int lkA = (lane >> 4) << 3;
    const int rB  = (lane & 7) + ((lane & 16) ? 8 : 0);
    const int lkB = (lane & 8) ? 8 : 0;

    for (int ks = 0; ks < nK; ks++) {
        const int slot = ks % 3;
        if (ks + 1 < nK) asm volatile("cp.async.wait_group 1;");
        else             asm volatile("cp.async.wait_group 0;");
        __syncthreads();
        if (ks + 2 < nK) load_stage((ks + 2) % 3, ks + 2);

        const uint32_t aB = sbase + (uint32_t)(slot * STGH) * 2;
        const uint32_t bB = aB + AH * 2;
        const uint32_t aAddr = aB + (uint32_t)((wm + lrA) * LDH + lkA) * 2;
        const uint32_t bAddr = bB + (uint32_t)((wn + rB) * LDH + lkB) * 2;

        uint32_t a[2][4][4], b[2][4][4];
        #pragma unroll
        for (int mt = 0; mt < 4; mt++)
            LDSM4(a[0][mt], aAddr + (uint32_t)(mt * 16 * LDH) * 2);
        #pragma unroll
        for (int np = 0; np < 4; np++)
            LDSM4(b[0][np], bAddr + (uint32_t)(np * 16 * LDH) * 2);

        #pragma unroll
        for (int kstep = 0; kstep < 4; kstep++) {
            const int cur = kstep & 1;
            if (kstep < 3) {
                const int nxt = cur ^ 1;
                #pragma unroll
                for (int mt = 0; mt < 4; mt++)
                    LDSM4(a[nxt][mt], aAddr + (uint32_t)(mt * 16 * LDH) * 2 + (kstep + 1) * 32);
                #pragma unroll
                for (int np = 0; np < 4; np++)
                    LDSM4(b[nxt][np], bAddr + (uint32_t)(np * 16 * LDH) * 2 + (kstep + 1) * 32);
            }
            #pragma unroll
            for (int mt = 0; mt < 4; mt++)
                #pragma unroll
                for (int nt = 0; nt < 8; nt++)
                    mma_h(acc[mt][nt], a[cur][mt], &b[cur][nt >> 1][(nt & 1) * 2]);
        }
    }

    // ---- epilogue ----
    #pragma unroll
    for (int mt = 0; mt < 4; mt++) {
        #pragma unroll
        for (int hf = 0; hf < 2; hf++) {
            const size_t row = (size_t)m0 + wm + mt * 16 + g + hf * 8;
            #pragma unroll
            for (int nt = 0; nt < 8; nt++) {
                const int col = n0 + wn + nt * 8 + tig * 2;
                float v0 = acc[mt][nt][hf * 2 + 0];
                float v1 = acc[mt][nt][hf * 2 + 1];
                if (EPI == EPI_QKVG) {
                    // [0,2048)=qk fp32  [2048,4096)=v half  [4096,6144)=g half(+bias)
                    if (n0 < 2048) {
                        *(float2*)((float*)Cv + row * 2048 + col) = make_float2(v0, v1);
                    } else if (n0 < 4096) {
                        __half* vhp = (__half*)(void*)resv;
                        *(__half2*)(vhp + row * 2048 + (col - 2048)) = __floats2half2_rn(v0, v1);
                    } else {
                        const int cl = col - 4096;
                        v0 += bias[cl]; v1 += bias[cl + 1];
                        __half* gp = (__half*)(void*)aux;
                        *(__half2*)(gp + row * 2048 + cl) = __floats2half2_rn(v0, v1);
                    }
                } else if (EPI == EPI_RES) {
                    const size_t base = row * (size_t)N + col;
                    const float2 rv = *(const float2*)((const float*)resv + base);
                    *(float2*)((float*)Cv + base) = make_float2(v0 + rv.x, v1 + rv.y);
                } else { // EPI_SWIGLU
                    ((__half*)Cv)[row * (size_t)(N >> 1) + (col >> 1)] =
                        __float2half_rn(siluf(v0) * v1);
                }
            }
        }
    }
}

// ------- 64x32 tiled transpose + fp16 convert, half2 wide stores -------
__global__ __launch_bounds__(256) void transpose_w(const float* __restrict__ in,
                                                   __half* __restrict__ out,
                                                   int R, int Ccols, float scale,
                                                   int rowMul, int rowOff)
{
    __shared__ float tile[64][33];
    const int c0 = blockIdx.x * 32, r0 = blockIdx.y * 64;
    const int x = threadIdx.x & 31, y = threadIdx.x >> 5;
    #pragma unroll
    for (int i = 0; i < 64; i += 8)
        tile[i + y][x] = in[(size_t)(r0 + i + y) * Ccols + c0 + x] * scale;
    __syncthreads();
    #pragma unroll
    for (int i = 0; i < 32; i += 8) {
        const int oc = i + y;
        __half2* dst = (__half2*)(out + ((size_t)(c0 + oc) * rowMul + rowOff) * R + r0);
        dst[x] = __floats2half2_rn(tile[2 * x][oc], tile[2 * x + 1][oc]);
    }
}

// ---------------- RMSNorm: fp32 in -> half out ----------------
__global__ __launch_bounds__(256) void rmsnorm_k(const float* __restrict__ x,
                                                 const float* __restrict__ w,
                                                 __half* __restrict__ y)
{
    const int row = blockIdx.x;
    const int tid = threadIdx.x;
    const float4* xr = (const float4*)(x + (size_t)row * D_MODEL);
    float4 v0 = xr[tid];
    float4 v1 = xr[tid + 256];
    float ss = v0.x*v0.x + v0.y*v0.y + v0.z*v0.z + v0.w*v0.w
             + v1.x*v1.x + v1.y*v1.y + v1.z*v1.z + v1.w*v1.w;
    #pragma unroll
    for (int off = 16; off; off >>= 1) ss += __shfl_xor_sync(0xffffffffu, ss, off);
    __shared__ float red[8];
    if ((tid & 31) == 0) red[tid >> 5] = ss;
    __syncthreads();
    if (tid < 32) {
        float t = (tid < 8) ? red[tid] : 0.f;
        #pragma unroll
        for (int off = 4; off; off >>= 1) t += __shfl_xor_sync(0xffffffffu, t, off);
        if (tid == 0) red[0] = t;
    }
    __syncthreads();
    const float scale = rsqrtf(red[0] * (1.f / (float)D_MODEL) + 1e-5f);
    const float4* wr = (const float4*)w;
    float4 w0 = wr[tid], w1 = wr[tid + 256];
    __half2* y2 = (__half2*)(y + (size_t)row * D_MODEL);
    y2[tid * 2]       = __floats2half2_rn(v0.x * scale * w0.x, v0.y * scale * w0.y);
    y2[tid * 2 + 1]   = __floats2half2_rn(v0.z * scale * w0.z, v0.w * scale * w0.w);
    y2[512 + tid * 2] = __floats2half2_rn(v1.x * scale * w1.x, v1.y * scale * w1.y);
    y2[513 + tid * 2] = __floats2half2_rn(v1.z * scale * w1.z, v1.w * scale * w1.w);
}

// ---- fused low-rank gate: t16 in-register, then eg = exp(logsigmoid(.)/16) ----
__global__ __launch_bounds__(256) void kg_fused(const __half* __restrict__ xn,
                                                const float* __restrict__ W1g,
                                                const float* __restrict__ W2g,
                                                const float* __restrict__ b,
                                                float* __restrict__ eg)
{
    const int gw = (blockIdx.x * 256 + threadIdx.x) >> 5;
    const int lane = threadIdx.x & 31;
    if (gw >= NTOK) return;
    const __half2* xr = (const __half2*)(xn + (size_t)gw * D_MODEL);
    float acc[16];
    #pragma unroll
    for (int j = 0; j < 16; j++) acc[j] = 0.f;
    for (int k2 = lane; k2 < 1024; k2 += 32) {
        const float2 xv = __half22float2(xr[k2]);
        const float4* w0r = (const float4*)(W1g + (size_t)(2 * k2) * 16);
        const float4* w1r = (const float4*)(W1g + (size_t)(2 * k2 + 1) * 16);
        float4 A0 = w0r[0], A1 = w0r[1], A2 = w0r[2], A3 = w0r[3];
        float4 B0 = w1r[0], B1 = w1r[1], B2 = w1r[2], B3 = w1r[3];
        acc[0]  = fmaf(xv.x, A0.x, fmaf(xv.y, B0.x, acc[0]));
        acc[1]  = fmaf(xv.x, A0.y, fmaf(xv.y, B0.y, acc[1]));
        acc[2]  = fmaf(xv.x, A0.z, fmaf(xv.y, B0.z, acc[2]));
        acc[3]  = fmaf(xv.x, A0.w, fmaf(xv.y, B0.w, acc[3]));
        acc[4]  = fmaf(xv.x, A1.x, fmaf(xv.y, B1.x, acc[4]));
        acc[5]  = fmaf(xv.x, A1.y, fmaf(xv.y, B1.y, acc[5]));
        acc[6]  = fmaf(xv.x, A1.z, fmaf(xv.y, B1.z, acc[6]));
        acc[7]  = fmaf(xv.x, A1.w, fmaf(xv.y, B1.w, acc[7]));
        acc[8]  = fmaf(xv.x, A2.x, fmaf(xv.y, B2.x, acc[8]));
        acc[9]  = fmaf(xv.x, A2.y, fmaf(xv.y, B2.y, acc[9]));
        acc[10] = fmaf(xv.x, A2.z, fmaf(xv.y, B2.z, acc[10]));
        acc[11] = fmaf(xv.x, A2.w, fmaf(xv.y, B2.w, acc[11]));
        acc[12] = fmaf(xv.x, A3.x, fmaf(xv.y, B3.x, acc[12]));
        acc[13] = fmaf(xv.x, A3.y, fmaf(xv.y, B3.y, acc[13]));
        acc[14] = fmaf(xv.x, A3.z, fmaf(xv.y, B3.z, acc[14]));
        acc[15] = fmaf(xv.x, A3.w, fmaf(xv.y, B3.w, acc[15]));
    }
    #pragma unroll
    for (int j = 0; j < 16; j++) {
        #pragma unroll
        for (int off = 16; off; off >>= 1)
            acc[j] += __shfl_xor_sync(0xffffffffu, acc[j], off);
    }
    float* ego = eg + (size_t)gw * 1024;
    #pragma unroll 4
    for (int nb = 0; nb < 32; nb++) {
        const int n = nb * 32 + lane;
        float z = b[n];
        #pragma unroll
        for (int j = 0; j < 16; j++) z = fmaf(acc[j], W2g[j * 1024 + n], z);
        const float ls = fminf(z, 0.f) - log1pf(__expf(-fabsf(z)));
        ego[n] = __expf(ls * 0.0625f);
    }
}

// ================ chunked GLA scan: 3 passes ================

// pass 1: per-chunk local state T and gate product P
__global__ __launch_bounds__(256) void scan_p1(const float* __restrict__ qk,
                                               const float* __restrict__ eg,
                                               const __half* __restrict__ vh,
                                               float* __restrict__ Tc,
                                               float* __restrict__ Pc)
{
    const int bhh = blockIdx.x;
    const int c   = blockIdx.y;
    const int bh = bhh >> 1, half = bhh & 1;
    const int b = bh >> 4, h = bh & 15;
    const int tid = threadIdx.x;
    const int dp = tid >> 2, g = tid & 3;

    __shared__ float sk[2][2][64], se[2][2][64], sv[2][2][64];
    float S[16], pe[16];
    #pragma unroll
    for (int j = 0; j < 16; j++) { S[j] = 0.f; pe[j] = 1.f; }

    const size_t tok0 = (size_t)b * LSEQ + (size_t)c * CLEN;
    const int i64 = tid & 63;
    const int sel = tid >> 6;

    auto loadslot = [&](int slot, int t0) {
        #pragma unroll
        for (int sub = 0; sub < 2; sub++) {
            const size_t base = tok0 + t0 + sub;
            if (sel == 1)      sk[slot][sub][i64] = qk[base * 2048 + 1024 + h * 64 + i64];
            else if (sel == 2) se[slot][sub][i64] = eg[base * 1024 + h * 64 + i64];
            else if (sel == 3) sv[slot][sub][i64] =
                __half2float(vh[base * 2048 + h * 128 + half * 64 + i64]);
        }
    };

    loadslot(0, 0);
    __syncthreads();
    for (int t = 0; t < CLEN; t += 2) {
        const int p = (t >> 1) & 1;
        if (t + 2 < CLEN) loadslot(p ^ 1, t + 2);
        #pragma unroll
        for (int sub = 0; sub < 2; sub++) {
            const float vv = sv[p][sub][dp];
            #pragma unroll
            for (int j = 0; j < 16; j++) {
                const int kk = g * 16 + j;
                const float e = se[p][sub][kk];
                S[j]  = fmaf(S[j], e, sk[p][sub][kk] * vv);
                pe[j] *= e;
            }
        }
        __syncthreads();
    }

    const size_t tb = (((size_t)c * 64 + bhh) * 64 + dp) * 64 + g * 16;
    #pragma unroll
    for (int j = 0; j < 16; j++) Tc[tb + j] = S[j];
    if (dp == 0) {
        const size_t pb = ((size_t)c * 64 + bhh) * 64 + g * 16;
        #pragma unroll
        for (int j = 0; j < 16; j++) Pc[pb + j] = pe[j];
    }
}

// pass 2: sequential chunk combine — one thread per (bhh, dp, j), 1024 blocks
__global__ __launch_bounds__(256) void scan_p2(const float* __restrict__ Tc,
                                               const float* __restrict__ Pc,
                                               float* __restrict__ Sst)
{
    const int idx = blockIdx.x * 256 + threadIdx.x;   // 0 .. 262143
    const int bhh = idx >> 12;                        // 64 bhh
    const int sub = idx & 4095;
    const int dp = sub >> 6, j = sub & 63;
    float S = 0.f;
    for (int c = 0; c < NCHUNK; c++) {
        const size_t tb = (((size_t)c * 64 + bhh) * 64 + dp) * 64 + j;
        const size_t pb = ((size_t)c * 64 + bhh) * 64 + j;
        Sst[tb] = S;
        S = fmaf(Pc[pb], S, Tc[tb]);
    }
}

// pass 3 (fused): replay chunk, groupnorm + silu(g half), write half oh (+ Sf last)
#define P3_SMEM ((128 * 128 + 3 * 256 + 512) * 4)   // 70656 B

__global__ __launch_bounds__(512) void scan_p3(const float* __restrict__ qk,
                                               const float* __restrict__ eg,
                                               const __half* __restrict__ vh,
                                               const float* __restrict__ Sst,
                                               const __half* __restrict__ gth,
                                               __half* __restrict__ oh,
                                               float* __restrict__ Sf)
{
    extern __shared__ __align__(16) float p3s[];
    float* obuf = p3s;
    float* sq   = obuf + 128 * 128;
    float* sk   = sq + 256;
    float* se   = sk + 256;
    float* sv   = se + 256;

    const int bh = blockIdx.x;
    const int c  = blockIdx.y;
    const int b = bh >> 4, h = bh & 15;
    const int tid = threadIdx.x;
    const int dp = tid >> 2;
    const int g  = tid & 3;

    float S[16];
    {
        const int bhh = bh * 2 + (dp >> 6);
        const size_t tb = (((size_t)c * 64 + bhh) * 64 + (dp & 63)) * 64 + g * 16;
        #pragma unroll
        for (int j = 0; j < 16; j++) S[j] = Sst[tb + j];
    }

    const size_t tok0 = (size_t)b * LSEQ + (size_t)c * CLEN;
    const int grp = tid >> 7;
    const int gi  = tid & 127;

    auto loadslot = [&](int slot, int t0) {
        if (grp == 3) {
            #pragma unroll
            for (int sub = 0; sub < 2; sub++)
                sv[(slot * 2 + sub) * 128 + gi] =
                    __half2float(vh[(tok0 + t0 + sub) * 2048 + h * 128 + gi]);
        } else {
            const int sub = gi >> 6, i64 = gi & 63;
            const size_t base = tok0 + t0 + sub;
            if (grp == 0)      sq[(slot * 2 + sub) * 64 + i64] = qk[base * 2048 + h * 64 + i64];
            else if (grp == 1) sk[(slot * 2 + sub) * 64 + i64] = qk[base * 2048 + 1024 + h * 64 + i64];
            else               se[(slot * 2 + sub) * 64 + i64] = eg[base * 1024 + h * 64 + i64];
        }
    };

    loadslot(0, 0);
    __syncthreads();
    for (int t = 0; t < CLEN; t += 2) {
        const int p = (t >> 1) & 1;
        if (t + 2 < CLEN) loadslot(p ^ 1, t + 2);
        #pragma unroll
        for (int sub = 0; sub < 2; sub++) {
            const float vv = sv[(p * 2 + sub) * 128 + dp];
            float acc = 0.f;
            #pragma unroll
            for (int j = 0; j < 16; j++) {
                const int kk = g * 16 + j;
                S[j] = fmaf(S[j], se[(p * 2 + sub) * 64 + kk], sk[(p * 2 + sub) * 64 + kk] * vv);
                acc  = fmaf(sq[(p * 2 + sub) * 64 + kk], S[j], acc);
            }
            acc += __shfl_xor_sync(0xffffffffu, acc, 1);
            acc += __shfl_xor_sync(0xffffffffu, acc, 2);
            if (g == 0) obuf[(t + sub) * 128 + dp] = acc;
        }
        __syncthreads();
    }

    if (c == NCHUNK - 1 && Sf) {
        #pragma unroll
        for (int j = 0; j < 16; j++) {
            const int kk = g * 16 + j;
            Sf[(((size_t)b * 16 + h) * 64 + kk) * 128 + dp] = S[j];
        }
    }

    const int w = tid >> 5, lane = tid & 31;
    #pragma unroll
    for (int i = 0; i < 8; i++) {
        const int t = w * 8 + i;
        const float4 ov = *(const float4*)(obuf + t * 128 + lane * 4);
        float s  = ov.x + ov.y + ov.z + ov.w;
        float ss = ov.x*ov.x + ov.y*ov.y + ov.z*ov.z + ov.w*ov.w;
        #pragma unroll
        for (int off = 16; off; off >>= 1) {
            s  += __shfl_xor_sync(0xffffffffu, s,  off);
            ss += __shfl_xor_sync(0xffffffffu, ss, off);
        }
        const float mu = s * (1.f / 128.f);
        const float rs = rsqrtf(ss * (1.f / 128.f) - mu * mu + 1e-5f);
        const size_t base = (tok0 + t) * 2048 + (size_t)h * 128 + lane * 4;
        const __half2* gv2 = (const __half2*)(gth + base);
        const float2 g01 = __half22float2(gv2[0]);
        const float2 g23 = __half22float2(gv2[1]);
        __half2* op = (__half2*)(oh + base);
        op[0] = __floats2half2_rn(siluf(g01.x) * ((ov.x - mu) * rs),
                                  siluf(g01.y) * ((ov.y - mu) * rs));
        op[1] = __floats2half2_rn(siluf(g23.x) * ((ov.z - mu) * rs),
                                  siluf(g23.y) * ((ov.w - mu) * rs));
    }
}

// ---------------- launch ----------------
extern "C" void kernel_launch(void* const* d_in, const int* in_sizes, int n_in,
                              void* d_out, int out_size)
{
    (void)in_sizes; (void)n_in;
    const float* x    = (const float*)d_in[0];
    const float* Wq   = (const float*)d_in[1];
    const float* Wk   = (const float*)d_in[2];
    const float* Wkg1 = (const float*)d_in[3];
    const float* Wkg2 = (const float*)d_in[4];
    const float* bkg2 = (const float*)d_in[5];
    const float* Wv   = (const float*)d_in[6];
    const float* Wg   = (const float*)d_in[7];
    const float* bg   = (const float*)d_in[8];
    const float* Wo   = (const float*)d_in[9];
    const float* ln1  = (const float*)d_in[10];
    const float* ln2  = (const float*)d_in[11];
    const float* W1   = (const float*)d_in[12];
    const float* W3   = (const float*)d_in[13];
    const float* W2   = (const float*)d_in[14];
    float* out = (float*)d_out;

    __half *xn, *vh, *gth, *oh, *h1h, *wt;
    float *qk, *egb, *x2, *Tc, *Pc, *Sst;
    cudaGetSymbolAddress((void**)&xn,  g_xn);
    cudaGetSymbolAddress((void**)&qk,  g_qk);
    cudaGetSymbolAddress((void**)&egb, g_eg);
    cudaGetSymbolAddress((void**)&vh,  g_vh);
    cudaGetSymbolAddress((void**)&gth, g_gth);
    cudaGetSymbolAddress((void**)&oh,  g_oh);
    cudaGetSymbolAddress((void**)&x2,  g_x2);
    cudaGetSymbolAddress((void**)&h1h, g_h1h);
    cudaGetSymbolAddress((void**)&wt,  g_wt);
    cudaGetSymbolAddress((void**)&Tc,  g_Tc);
    cudaGetSymbolAddress((void**)&Pc,  g_Pc);
    cudaGetSymbolAddress((void**)&Sst, g_Sst);

    __half* wqkvgT = wt;                           // [6144][2048]
    __half* woT    = wqkvgT + (size_t)6144 * 2048;
    __half* w13T   = woT    + (size_t)2048 * 2048; // [11264][2048] interleaved
    __half* w2T    = w13T   + (size_t)11264 * 2048;

    cudaFuncSetAttribute(gemm_h<EPI_QKVG  >, cudaFuncAttributeMaxDynamicSharedMemorySize, GSMEM);
    cudaFuncSetAttribute(gemm_h<EPI_RES   >, cudaFuncAttributeMaxDynamicSharedMemorySize, GSMEM);
    cudaFuncSetAttribute(gemm_h<EPI_SWIGLU>, cudaFuncAttributeMaxDynamicSharedMemorySize, GSMEM);
    cudaFuncSetAttribute(scan_p3, cudaFuncAttributeMaxDynamicSharedMemorySize, P3_SMEM);

    const size_t xElems  = (size_t)NTOK * D_MODEL;
    const size_t sfElems = (size_t)BDIM * NHEAD * 64 * 128;
    float* Sf = ((size_t)out_size >= xElems + sfElems) ? (out + xElems) : nullptr;

    const float kscale = 0.08838834764831843f;

    transpose_w<<<dim3(32, 32), 256>>>(Wq, wqkvgT,                     2048, 1024, 1.f,    1, 0);
    transpose_w<<<dim3(32, 32), 256>>>(Wk, wqkvgT + (size_t)1024*2048, 2048, 1024, kscale, 1, 0);
    transpose_w<<<dim3(64, 32), 256>>>(Wv, wqkvgT + (size_t)2048*2048, 2048, 2048, 1.f,    1, 0);
    transpose_w<<<dim3(64, 32), 256>>>(Wg, wqkvgT + (size_t)4096*2048, 2048, 2048, 1.f,    1, 0);

    rmsnorm_k<<<NTOK, 256>>>(x, ln1, xn);

    gemm_h<EPI_QKVG><<<dim3(48, 64), 128, GSMEM>>>(
        xn, wqkvgT, qk, NTOK, 6144, 2048, bg, vh, (const float*)gth);

    transpose_w<<<dim3(64,  32), 256>>>(Wo, woT,  2048, 2048, 1.f, 1, 0);
    transpose_w<<<dim3(176, 32), 256>>>(W1, w13T, 2048, 5632, 1.f, 2, 0);
    transpose_w<<<dim3(176, 32), 256>>>(W3, w13T, 2048, 5632, 1.f, 2, 1);
    transpose_w<<<dim3(64,  88), 256>>>(W2, w2T,  5632, 2048, 1.f, 1, 0);

    kg_fused<<<NTOK / 8, 256>>>(xn, Wkg1, Wkg2, bkg2, egb);

    scan_p1<<<dim3(64, NCHUNK), 256>>>(qk, egb, vh, Tc, Pc);
    scan_p2<<<1024, 256>>>(Tc, Pc, Sst);
    scan_p3<<<dim3(32, NCHUNK), 512, P3_SMEM>>>(qk, egb, vh, Sst, gth, oh, Sf);

    gemm_h<EPI_RES><<<dim3(16, 64), 128, GSMEM>>>(
        oh, woT, x2, NTOK, 2048, 2048, nullptr, x, nullptr);

    rmsnorm_k<<<NTOK, 256>>>(x2, ln2, xn);

    gemm_h<EPI_SWIGLU><<<dim3(88, 64), 128, GSMEM>>>(
        xn, w13T, h1h, NTOK, 11264, 2048, nullptr, nullptr, nullptr);

    gemm_h<EPI_RES><<<dim3(16, 64), 128, GSMEM>>>(
        h1h, w2T, out, NTOK, D_MODEL, HIDDEN, nullptr, x2, nullptr);
}

// round 17
// speedup vs baseline: 1.0263x; 1.0263x over previous
#include <cuda_runtime.h>
#include <cuda_fp16.h>
#include <cstdint>
#include <cstddef>

#define D_MODEL 2048
#define LSEQ    4096
#define BDIM    2
#define NTOK    (BDIM * LSEQ)      // 8192
#define NHEAD   16
#define HIDDEN  5632
#define NCHUNK  32
#define CLEN    (LSEQ / NCHUNK)    // 128

// ---------------- scratch (device globals; no allocation allowed) ----------------
__device__ __half g_xn [(size_t)NTOK * D_MODEL];
__device__ __half g_qkh[(size_t)NTOK * 2048];             // q | k*scale (half)
__device__ float  g_eg [(size_t)NTOK * 1024];
__device__ __half g_vh [(size_t)NTOK * D_MODEL];          // v (half)
__device__ __half g_gth[(size_t)NTOK * D_MODEL];          // g (half, bias included)
__device__ __half g_oh [(size_t)NTOK * D_MODEL];
__device__ float  g_x2 [(size_t)NTOK * D_MODEL];
__device__ __half g_h1h[(size_t)NTOK * HIDDEN];
__device__ __half g_wt [51380224];
__device__ float  g_Tc [(size_t)NCHUNK * 64 * 64 * 64];
__device__ float  g_Pc [(size_t)NCHUNK * 64 * 64];
__device__ float  g_Sst[(size_t)NCHUNK * 64 * 64 * 64];

__device__ __forceinline__ float siluf(float x) { return x / (1.f + __expf(-x)); }
__device__ __forceinline__ void cpa16(void* s, const void* g) {
    uint32_t a = (uint32_t)__cvta_generic_to_shared(s);
    asm volatile("cp.async.cg.shared.global [%0], [%1], 16;" :: "r"(a), "l"(g));
}

// ================= fp16 tensor-core GEMM (R10/R12 proven mainloop) =================
enum { EPI_QKVG = 0, EPI_RES = 3, EPI_SWIGLU = 5 };

#define BK    64
#define LDH   72
#define AH    (128 * LDH)
#define STGH  (2 * AH)
#define NST   3
#define GSMEM (NST * STGH * 2)             // 110592 B

#define LDSM4(r, a)                                                            \
    asm volatile("ldmatrix.sync.aligned.m8n8.x4.shared.b16 {%0,%1,%2,%3}, [%4];" \
        : "=r"((r)[0]), "=r"((r)[1]), "=r"((r)[2]), "=r"((r)[3]) : "r"(a))

__device__ __forceinline__ void mma_h(float* c, const uint32_t* a, const uint32_t* b) {
    asm volatile(
        "mma.sync.aligned.m16n8k16.row.col.f32.f16.f16.f32 "
        "{%0,%1,%2,%3}, {%4,%5,%6,%7}, {%8,%9}, {%0,%1,%2,%3};"
        : "+f"(c[0]), "+f"(c[1]), "+f"(c[2]), "+f"(c[3])
        : "r"(a[0]), "r"(a[1]), "r"(a[2]), "r"(a[3]), "r"(b[0]), "r"(b[1]));
}

template <int EPI>
__global__ __launch_bounds__(128, 2) void gemm_h(
    const __half* __restrict__ A, const __half* __restrict__ Wt, void* __restrict__ Cv,
    int M, int N, int K,
    const float* __restrict__ bias, const void* __restrict__ resv,
    const float* __restrict__ aux)
{
    extern __shared__ __align__(16) __half hsm[];
    const int tid = threadIdx.x;
    const int wid = tid >> 5, lane = tid & 31;
    const int g = lane >> 2, tig = lane & 3;
    const int wm = (wid >> 1) * 64;
    const int wn = (wid & 1) * 64;
    const int m0 = blockIdx.y * 128;
    const int n0 = blockIdx.x * 128;
    const int nK = K >> 6;

    auto load_stage = [&](int slot, int kc) {
        __half* As = hsm + slot * STGH;
        __half* Bs = As + AH;
        const int k0 = kc * BK;
        const __half* Ag = A  + (size_t)m0 * K + k0;
        const __half* Bg = Wt + (size_t)n0 * K + k0;
        #pragma unroll
        for (int j = 0; j < 8; j++) {
            const int i = tid + j * 128;
            const int row = i >> 3, c = i & 7;
            cpa16(As + row * LDH + c * 8, Ag + (size_t)row * K + c * 8);
            cpa16(Bs + row * LDH + c * 8, Bg + (size_t)row * K + c * 8);
        }
        asm volatile("cp.async.commit_group;");
    };

    float acc[4][8][4];
    #pragma unroll
    for (int mt = 0; mt < 4; mt++)
        #pragma unroll
        for (int nt = 0; nt < 8; nt++)
            #pragma unroll
            for (int r = 0; r < 4; r++) acc[mt][nt][r] = 0.f;

    load_stage(0, 0);
    load_stage(1, 1);

    const uint32_t sbase = (uint32_t)__cvta_generic_to_shared(hsm);
    const int lrA = lane & 15;
    const int lkA = (lane >> 4) << 3;
    const int rB  = (lane & 7) + ((lane & 16) ? 8 : 0);
    const int lkB = (lane & 8) ? 8 : 0;

    for (int ks = 0; ks < nK; ks++) {
        const int slot = ks % 3;
        if (ks + 1 < nK) asm volatile("cp.async.wait_group 1;");
        else             asm volatile("cp.async.wait_group 0;");
        __syncthreads();
        if (ks + 2 < nK) load_stage((ks + 2) % 3, ks + 2);

        const uint32_t aB = sbase + (uint32_t)(slot * STGH) * 2;
        const uint32_t bB = aB + AH * 2;
        const uint32_t aAddr = aB + (uint32_t)((wm + lrA) * LDH + lkA) * 2;
        const uint32_t bAddr = bB + (uint32_t)((wn + rB) * LDH + lkB) * 2;

        uint32_t a[2][4][4], b[2][4][4];
        #pragma unroll
        for (int mt = 0; mt < 4; mt++)
            LDSM4(a[0][mt], aAddr + (uint32_t)(mt * 16 * LDH) * 2);
        #pragma unroll
        for (int np = 0; np < 4; np++)
            LDSM4(b[0][np], bAddr + (uint32_t)(np * 16 * LDH) * 2);

        #pragma unroll
        for (int kstep = 0; kstep < 4; kstep++) {
            const int cur = kstep & 1;
            if (kstep < 3) {
                const int nxt = cur ^ 1;
                #pragma unroll
                for (int mt = 0; mt < 4; mt++)
                    LDSM4(a[nxt][mt], aAddr + (uint32_t)(mt * 16 * LDH) * 2 + (kstep + 1) * 32);
                #pragma unroll
                for (int np = 0; np < 4; np++)
                    LDSM4(b[nxt][np], bAddr + (uint32_t)(np * 16 * LDH) * 2 + (kstep + 1) * 32);
            }
            #pragma unroll
            for (int mt = 0; mt < 4; mt++)
                #pragma unroll
                for (int nt = 0; nt < 8; nt++)
                    mma_h(acc[mt][nt], a[cur][mt], &b[cur][nt >> 1][(nt & 1) * 2]);
        }
    }

    // ---- epilogue ----
    #pragma unroll
    for (int mt = 0; mt < 4; mt++) {
        #pragma unroll
        for (int hf = 0; hf < 2; hf++) {
            const size_t row = (size_t)m0 + wm + mt * 16 + g + hf * 8;
            #pragma unroll
            for (int nt = 0; nt < 8; nt++) {
                const int col = n0 + wn + nt * 8 + tig * 2;
                float v0 = acc[mt][nt][hf * 2 + 0];
                float v1 = acc[mt][nt][hf * 2 + 1];
                if (EPI == EPI_QKVG) {
                    // all half: [0,2048)=qk  [2048,4096)=v  [4096,6144)=g(+bias)
                    if (n0 < 2048) {
                        __half* qp = (__half*)Cv;
                        *(__half2*)(qp + row * 2048 + col) = __floats2half2_rn(v0, v1);
                    } else if (n0 < 4096) {
                        __half* vhp = (__half*)(void*)resv;
                        *(__half2*)(vhp + row * 2048 + (col - 2048)) = __floats2half2_rn(v0, v1);
                    } else {
                        const int cl = col - 4096;
                        v0 += bias[cl]; v1 += bias[cl + 1];
                        __half* gp = (__half*)(void*)aux;
                        *(__half2*)(gp + row * 2048 + cl) = __floats2half2_rn(v0, v1);
                    }
                } else if (EPI == EPI_RES) {
                    const size_t base = row * (size_t)N + col;
                    const float2 rv = *(const float2*)((const float*)resv + base);
                    *(float2*)((float*)Cv + base) = make_float2(v0 + rv.x, v1 + rv.y);
                } else { // EPI_SWIGLU
                    ((__half*)Cv)[row * (size_t)(N >> 1) + (col >> 1)] =
                        __float2half_rn(siluf(v0) * v1);
                }
            }
        }
    }
}

// ------- merged weight transpose: all 8 weights in ONE launch -------
// flat 1D grid; each segment: 64x32 tile transpose with half2 wide stores.
struct TransSeg {
    const float* src; __half* dst;
    int nbx;          // C/32
    int start;        // first flat block
    int R, Ccols;
    float scale;
    int rowMul, rowOff;
};
struct TransTable { TransSeg seg[8]; };

__global__ __launch_bounds__(256) void transpose_all(TransTable tt)
{
    __shared__ float tile[64][33];
    const int fb = blockIdx.x;
    // find segment (8-way linear scan; trivial cost)
    int si = 0;
    #pragma unroll
    for (int i = 1; i < 8; i++) if (fb >= tt.seg[i].start) si = i;
    const TransSeg sgm = tt.seg[si];
    const int lb = fb - sgm.start;
    const int bx = lb % sgm.nbx, by = lb / sgm.nbx;
    const int c0 = bx * 32, r0 = by * 64;
    const int x = threadIdx.x & 31, y = threadIdx.x >> 5;
    #pragma unroll
    for (int i = 0; i < 64; i += 8)
        tile[i + y][x] = sgm.src[(size_t)(r0 + i + y) * sgm.Ccols + c0 + x] * sgm.scale;
    __syncthreads();
    #pragma unroll
    for (int i = 0; i < 32; i += 8) {
        const int oc = i + y;
        __half2* dst = (__half2*)(sgm.dst +
            ((size_t)(c0 + oc) * sgm.rowMul + sgm.rowOff) * sgm.R + r0);
        dst[x] = __floats2half2_rn(tile[2 * x][oc], tile[2 * x + 1][oc]);
    }
}

// ---------------- RMSNorm: fp32 in -> half out ----------------
__global__ __launch_bounds__(256) void rmsnorm_k(const float* __restrict__ x,
                                                 const float* __restrict__ w,
                                                 __half* __restrict__ y)
{
    const int row = blockIdx.x;
    const int tid = threadIdx.x;
    const float4* xr = (const float4*)(x + (size_t)row * D_MODEL);
    float4 v0 = xr[tid];
    float4 v1 = xr[tid + 256];
    float ss = v0.x*v0.x + v0.y*v0.y + v0.z*v0.z + v0.w*v0.w
             + v1.x*v1.x + v1.y*v1.y + v1.z*v1.z + v1.w*v1.w;
    #pragma unroll
    for (int off = 16; off; off >>= 1) ss += __shfl_xor_sync(0xffffffffu, ss, off);
    __shared__ float red[8];
    if ((tid & 31) == 0) red[tid >> 5] = ss;
    __syncthreads();
    if (tid < 32) {
        float t = (tid < 8) ? red[tid] : 0.f;
        #pragma unroll
        for (int off = 4; off; off >>= 1) t += __shfl_xor_sync(0xffffffffu, t, off);
        if (tid == 0) red[0] = t;
    }
    __syncthreads();
    const float scale = rsqrtf(red[0] * (1.f / (float)D_MODEL) + 1e-5f);
    const float4* wr = (const float4*)w;
    float4 w0 = wr[tid], w1 = wr[tid + 256];
    __half2* y2 = (__half2*)(y + (size_t)row * D_MODEL);
    y2[tid * 2]       = __floats2half2_rn(v0.x * scale * w0.x, v0.y * scale * w0.y);
    y2[tid * 2 + 1]   = __floats2half2_rn(v0.z * scale * w0.z, v0.w * scale * w0.w);
    y2[512 + tid * 2] = __floats2half2_rn(v1.x * scale * w1.x, v1.y * scale * w1.y);
    y2[513 + tid * 2] = __floats2half2_rn(v1.z * scale * w1.z, v1.w * scale * w1.w);
}

// ---- fused low-rank gate: t16 in-register, then eg = exp(logsigmoid(.)/16) ----
__global__ __launch_bounds__(256) void kg_fused(const __half* __restrict__ xn,
                                                const float* __restrict__ W1g,
                                                const float* __restrict__ W2g,
                                                const float* __restrict__ b,
                                                float* __restrict__ eg)
{
    const int gw = (blockIdx.x * 256 + threadIdx.x) >> 5;
    const int lane = threadIdx.x & 31;
    if (gw >= NTOK) return;
    const __half2* xr = (const __half2*)(xn + (size_t)gw * D_MODEL);
    float acc[16];
    #pragma unroll
    for (int j = 0; j < 16; j++) acc[j] = 0.f;
    for (int k2 = lane; k2 < 1024; k2 += 32) {
        const float2 xv = __half22float2(xr[k2]);
        const float4* w0r = (const float4*)(W1g + (size_t)(2 * k2) * 16);
        const float4* w1r = (const float4*)(W1g + (size_t)(2 * k2 + 1) * 16);
        float4 A0 = w0r[0], A1 = w0r[1], A2 = w0r[2], A3 = w0r[3];
        float4 B0 = w1r[0], B1 = w1r[1], B2 = w1r[2], B3 = w1r[3];
        acc[0]  = fmaf(xv.x, A0.x, fmaf(xv.y, B0.x, acc[0]));
        acc[1]  = fmaf(xv.x, A0.y, fmaf(xv.y, B0.y, acc[1]));
        acc[2]  = fmaf(xv.x, A0.z, fmaf(xv.y, B0.z, acc[2]));
        acc[3]  = fmaf(xv.x, A0.w, fmaf(xv.y, B0.w, acc[3]));
        acc[4]  = fmaf(xv.x, A1.x, fmaf(xv.y, B1.x, acc[4]));
        acc[5]  = fmaf(xv.x, A1.y, fmaf(xv.y, B1.y, acc[5]));
        acc[6]  = fmaf(xv.x, A1.z, fmaf(xv.y, B1.z, acc[6]));
        acc[7]  = fmaf(xv.x, A1.w, fmaf(xv.y, B1.w, acc[7]));
        acc[8]  = fmaf(xv.x, A2.x, fmaf(xv.y, B2.x, acc[8]));
        acc[9]  = fmaf(xv.x, A2.y, fmaf(xv.y, B2.y, acc[9]));
        acc[10] = fmaf(xv.x, A2.z, fmaf(xv.y, B2.z, acc[10]));
        acc[11] = fmaf(xv.x, A2.w, fmaf(xv.y, B2.w, acc[11]));
        acc[12] = fmaf(xv.x, A3.x, fmaf(xv.y, B3.x, acc[12]));
        acc[13] = fmaf(xv.x, A3.y, fmaf(xv.y, B3.y, acc[13]));
        acc[14] = fmaf(xv.x, A3.z, fmaf(xv.y, B3.z, acc[14]));
        acc[15] = fmaf(xv.x, A3.w, fmaf(xv.y, B3.w, acc[15]));
    }
    #pragma unroll
    for (int j = 0; j < 16; j++) {
        #pragma unroll
        for (int off = 16; off; off >>= 1)
            acc[j] += __shfl_xor_sync(0xffffffffu, acc[j], off);
    }
    float* ego = eg + (size_t)gw * 1024;
    #pragma unroll 4
    for (int nb = 0; nb < 32; nb++) {
        const int n = nb * 32 + lane;
        float z = b[n];
        #pragma unroll
        for (int j = 0; j < 16; j++) z = fmaf(acc[j], W2g[j * 1024 + n], z);
        const float ls = fminf(z, 0.f) - log1pf(__expf(-fabsf(z)));
        ego[n] = __expf(ls * 0.0625f);
    }
}

// ================ chunked GLA scan: 3 passes ================

// pass 1: per-chunk local state T and gate product P (k from half qk buffer)
__global__ __launch_bounds__(256) void scan_p1(const __half* __restrict__ qk,
                                               const float* __restrict__ eg,
                                               const __half* __restrict__ vh,
                                               float* __restrict__ Tc,
                                               float* __restrict__ Pc)
{
    const int bhh = blockIdx.x;
    const int c   = blockIdx.y;
    const int bh = bhh >> 1, half = bhh & 1;
    const int b = bh >> 4, h = bh & 15;
    const int tid = threadIdx.x;
    const int dp = tid >> 2, g = tid & 3;

    __shared__ float sk[2][2][64], se[2][2][64], sv[2][2][64];
    float S[16], pe[16];
    #pragma unroll
    for (int j = 0; j < 16; j++) { S[j] = 0.f; pe[j] = 1.f; }

    const size_t tok0 = (size_t)b * LSEQ + (size_t)c * CLEN;
    const int i64 = tid & 63;
    const int sel = tid >> 6;

    auto loadslot = [&](int slot, int t0) {
        #pragma unroll
        for (int sub = 0; sub < 2; sub++) {
            const size_t base = tok0 + t0 + sub;
            if (sel == 1)      sk[slot][sub][i64] =
                __half2float(qk[base * 2048 + 1024 + h * 64 + i64]);
            else if (sel == 2) se[slot][sub][i64] = eg[base * 1024 + h * 64 + i64];
            else if (sel == 3) sv[slot][sub][i64] =
                __half2float(vh[base * 2048 + h * 128 + half * 64 + i64]);
        }
    };

    loadslot(0, 0);
    __syncthreads();
    for (int t = 0; t < CLEN; t += 2) {
        const int p = (t >> 1) & 1;
        if (t + 2 < CLEN) loadslot(p ^ 1, t + 2);
        #pragma unroll
        for (int sub = 0; sub < 2; sub++) {
            const float vv = sv[p][sub][dp];
            #pragma unroll
            for (int j = 0; j < 16; j++) {
                const int kk = g * 16 + j;
                const float e = se[p][sub][kk];
                S[j]  = fmaf(S[j], e, sk[p][sub][kk] * vv);
                pe[j] *= e;
            }
        }
        __syncthreads();
    }

    const size_t tb = (((size_t)c * 64 + bhh) * 64 + dp) * 64 + g * 16;
    #pragma unroll
    for (int j = 0; j < 16; j++) Tc[tb + j] = S[j];
    if (dp == 0) {
        const size_t pb = ((size_t)c * 64 + bhh) * 64 + g * 16;
        #pragma unroll
        for (int j = 0; j < 16; j++) Pc[pb + j] = pe[j];
    }
}

// pass 2: sequential chunk combine — one thread per (bhh, dp, j)
__global__ __launch_bounds__(256) void scan_p2(const float* __restrict__ Tc,
                                               const float* __restrict__ Pc,
                                               float* __restrict__ Sst)
{
    const int idx = blockIdx.x * 256 + threadIdx.x;
    const int bhh = idx >> 12;
    const int sub = idx & 4095;
    const int dp = sub >> 6, j = sub & 63;
    float S = 0.f;
    for (int c = 0; c < NCHUNK; c++) {
        const size_t tb = (((size_t)c * 64 + bhh) * 64 + dp) * 64 + j;
        const size_t pb = ((size_t)c * 64 + bhh) * 64 + j;
        Sst[tb] = S;
        S = fmaf(Pc[pb], S, Tc[tb]);
    }
}

// pass 3 (fused): replay chunk, groupnorm + silu(g half), write half oh (+ Sf last)
#define P3_SMEM ((128 * 128 + 3 * 256 + 512) * 4)   // 70656 B

__global__ __launch_bounds__(512) void scan_p3(const __half* __restrict__ qk,
                                               const float* __restrict__ eg,
                                               const __half* __restrict__ vh,
                                               const float* __restrict__ Sst,
                                               const __half* __restrict__ gth,
                                               __half* __restrict__ oh,
                                               float* __restrict__ Sf)
{
    extern __shared__ __align__(16) float p3s[];
    float* obuf = p3s;
    float* sq   = obuf + 128 * 128;
    float* sk   = sq + 256;
    float* se   = sk + 256;
    float* sv   = se + 256;

    const int bh = blockIdx.x;
    const int c  = blockIdx.y;
    const int b = bh >> 4, h = bh & 15;
    const int tid = threadIdx.x;
    const int dp = tid >> 2;
    const int g  = tid & 3;

    float S[16];
    {
        const int bhh = bh * 2 + (dp >> 6);
        const size_t tb = (((size_t)c * 64 + bhh) * 64 + (dp & 63)) * 64 + g * 16;
        #pragma unroll
        for (int j = 0; j < 16; j++) S[j] = Sst[tb + j];
    }

    const size_t tok0 = (size_t)b * LSEQ + (size_t)c * CLEN;
    const int grp = tid >> 7;
    const int gi  = tid & 127;

    auto loadslot = [&](int slot, int t0) {
        if (grp == 3) {
            #pragma unroll
            for (int sub = 0; sub < 2; sub++)
                sv[(slot * 2 + sub) * 128 + gi] =
                    __half2float(vh[(tok0 + t0 + sub) * 2048 + h * 128 + gi]);
        } else {
            const int sub = gi >> 6, i64 = gi & 63;
            const size_t base = tok0 + t0 + sub;
            if (grp == 0)      sq[(slot * 2 + sub) * 64 + i64] =
                __half2float(qk[base * 2048 + h * 64 + i64]);
            else if (grp == 1) sk[(slot * 2 + sub) * 64 + i64] =
                __half2float(qk[base * 2048 + 1024 + h * 64 + i64]);
            else               se[(slot * 2 + sub) * 64 + i64] = eg[base * 1024 + h * 64 + i64];
        }
    };

    loadslot(0, 0);
    __syncthreads();
    for (int t = 0; t < CLEN; t += 2) {
        const int p = (t >> 1) & 1;
        if (t + 2 < CLEN) loadslot(p ^ 1, t + 2);
        #pragma unroll
        for (int sub = 0; sub < 2; sub++) {
            const float vv = sv[(p * 2 + sub) * 128 + dp];
            float acc = 0.f;
            #pragma unroll
            for (int j = 0; j < 16; j++) {
                const int kk = g * 16 + j;
                S[j] = fmaf(S[j], se[(p * 2 + sub) * 64 + kk], sk[(p * 2 + sub) * 64 + kk] * vv);
                acc  = fmaf(sq[(p * 2 + sub) * 64 + kk], S[j], acc);
            }
            acc += __shfl_xor_sync(0xffffffffu, acc, 1);
            acc += __shfl_xor_sync(0xffffffffu, acc, 2);
            if (g == 0) obuf[(t + sub) * 128 + dp] = acc;
        }
        __syncthreads();
    }

    if (c == NCHUNK - 1 && Sf) {
        #pragma unroll
        for (int j = 0; j < 16; j++) {
            const int kk = g * 16 + j;
            Sf[(((size_t)b * 16 + h) * 64 + kk) * 128 + dp] = S[j];
        }
    }

    const int w = tid >> 5, lane = tid & 31;
    #pragma unroll
    for (int i = 0; i < 8; i++) {
        const int t = w * 8 + i;
        const float4 ov = *(const float4*)(obuf + t * 128 + lane * 4);
        float s  = ov.x + ov.y + ov.z + ov.w;
        float ss = ov.x*ov.x + ov.y*ov.y + ov.z*ov.z + ov.w*ov.w;
        #pragma unroll
        for (int off = 16; off; off >>= 1) {
            s  += __shfl_xor_sync(0xffffffffu, s,  off);
            ss += __shfl_xor_sync(0xffffffffu, ss, off);
        }
        const float mu = s * (1.f / 128.f);
        const float rs = rsqrtf(ss * (1.f / 128.f) - mu * mu + 1e-5f);
        const size_t base = (tok0 + t) * 2048 + (size_t)h * 128 + lane * 4;
        const __half2* gv2 = (const __half2*)(gth + base);
        const float2 g01 = __half22float2(gv2[0]);
        const float2 g23 = __half22float2(gv2[1]);
        __half2* op = (__half2*)(oh + base);
        op[0] = __floats2half2_rn(siluf(g01.x) * ((ov.x - mu) * rs),
                                  siluf(g01.y) * ((ov.y - mu) * rs));
        op[1] = __floats2half2_rn(siluf(g23.x) * ((ov.z - mu) * rs),
                                  siluf(g23.y) * ((ov.w - mu) * rs));
    }
}

// ---------------- launch ----------------
extern "C" void kernel_launch(void* const* d_in, const int* in_sizes, int n_in,
                              void* d_out, int out_size)
{
    (void)in_sizes; (void)n_in;
    const float* x    = (const float*)d_in[0];
    const float* Wq   = (const float*)d_in[1];
    const float* Wk   = (const float*)d_in[2];
    const float* Wkg1 = (const float*)d_in[3];
    const float* Wkg2 = (const float*)d_in[4];
    const float* bkg2 = (const float*)d_in[5];
    const float* Wv   = (const float*)d_in[6];
    const float* Wg   = (const float*)d_in[7];
    const float* bg   = (const float*)d_in[8];
    const float* Wo   = (const float*)d_in[9];
    const float* ln1  = (const float*)d_in[10];
    const float* ln2  = (const float*)d_in[11];
    const float* W1   = (const float*)d_in[12];
    const float* W3   = (const float*)d_in[13];
    const float* W2   = (const float*)d_in[14];
    float* out = (float*)d_out;

    __half *xn, *qkh, *vh, *gth, *oh, *h1h, *wt;
    float *egb, *x2, *Tc, *Pc, *Sst;
    cudaGetSymbolAddress((void**)&xn,  g_xn);
    cudaGetSymbolAddress((void**)&qkh, g_qkh);
    cudaGetSymbolAddress((void**)&egb, g_eg);
    cudaGetSymbolAddress((void**)&vh,  g_vh);
    cudaGetSymbolAddress((void**)&gth, g_gth);
    cudaGetSymbolAddress((void**)&oh,  g_oh);
    cudaGetSymbolAddress((void**)&x2,  g_x2);
    cudaGetSymbolAddress((void**)&h1h, g_h1h);
    cudaGetSymbolAddress((void**)&wt,  g_wt);
    cudaGetSymbolAddress((void**)&Tc,  g_Tc);
    cudaGetSymbolAddress((void**)&Pc,  g_Pc);
    cudaGetSymbolAddress((void**)&Sst, g_Sst);

    __half* wqkvgT = wt;                           // [6144][2048]
    __half* woT    = wqkvgT + (size_t)6144 * 2048;
    __half* w13T   = woT    + (size_t)2048 * 2048; // [11264][2048] interleaved
    __half* w2T    = w13T   + (size_t)11264 * 2048;

    cudaFuncSetAttribute(gemm_h<EPI_QKVG  >, cudaFuncAttributeMaxDynamicSharedMemorySize, GSMEM);
    cudaFuncSetAttribute(gemm_h<EPI_RES   >, cudaFuncAttributeMaxDynamicSharedMemorySize, GSMEM);
    cudaFuncSetAttribute(gemm_h<EPI_SWIGLU>, cudaFuncAttributeMaxDynamicSharedMemorySize, GSMEM);
    cudaFuncSetAttribute(scan_p3, cudaFuncAttributeMaxDynamicSharedMemorySize, P3_SMEM);

    const size_t xElems  = (size_t)NTOK * D_MODEL;
    const size_t sfElems = (size_t)BDIM * NHEAD * 64 * 128;
    float* Sf = ((size_t)out_size >= xElems + sfElems) ? (out + xElems) : nullptr;

    const float kscale = 0.08838834764831843f;

    // ---- all 8 weight transposes in one launch ----
    TransTable tt;
    int cursor = 0;
    auto addseg = [&](int i, const float* src, __half* dst, int R, int C,
                      float sc, int rm, int ro) {
        tt.seg[i].src = src; tt.seg[i].dst = dst;
        tt.seg[i].nbx = C / 32; tt.seg[i].start = cursor;
        tt.seg[i].R = R; tt.seg[i].Ccols = C;
        tt.seg[i].scale = sc; tt.seg[i].rowMul = rm; tt.seg[i].rowOff = ro;
        cursor += (C / 32) * (R / 64);
    };
    addseg(0, Wq, wqkvgT,                     2048, 1024, 1.f,    1, 0);
    addseg(1, Wk, wqkvgT + (size_t)1024*2048, 2048, 1024, kscale, 1, 0);
    addseg(2, Wv, wqkvgT + (size_t)2048*2048, 2048, 2048, 1.f,    1, 0);
    addseg(3, Wg, wqkvgT + (size_t)4096*2048, 2048, 2048, 1.f,    1, 0);
    addseg(4, Wo, woT,  2048, 2048, 1.f, 1, 0);
    addseg(5, W1, w13T, 2048, 5632, 1.f, 2, 0);
    addseg(6, W3, w13T, 2048, 5632, 1.f, 2, 1);
    addseg(7, W2, w2T,  5632, 2048, 1.f, 1, 0);
    transpose_all<<<cursor, 256>>>(tt);

    rmsnorm_k<<<NTOK, 256>>>(x, ln1, xn);

    gemm_h<EPI_QKVG><<<dim3(48, 64), 128, GSMEM>>>(
        xn, wqkvgT, qkh, NTOK, 6144, 2048, bg, vh, (const float*)gth);

    kg_fused<<<NTOK / 8, 256>>>(xn, Wkg1, Wkg2, bkg2, egb);

    scan_p1<<<dim3(64, NCHUNK), 256>>>(qkh, egb, vh, Tc, Pc);
    scan_p2<<<1024, 256>>>(Tc, Pc, Sst);
    scan_p3<<<dim3(32, NCHUNK), 512, P3_SMEM>>>(qkh, egb, vh, Sst, gth, oh, Sf);

    gemm_h<EPI_RES><<<dim3(16, 64), 128, GSMEM>>>(
        oh, woT, x2, NTOK, 2048, 2048, nullptr, x, nullptr);

    rmsnorm_k<<<NTOK, 256>>>(x2, ln2, xn);

    gemm_h<EPI_SWIGLU><<<dim3(88, 64), 128, GSMEM>>>(
        xn, w13T, h1h, NTOK, 11264, 2048, nullptr, nullptr, nullptr);

    gemm_h<EPI_RES><<<dim3(16, 64), 128, GSMEM>>>(
        h1h, w2T, out, NTOK, D_MODEL, HIDDEN, nullptr, x2, nullptr);
}